// round 15
// baseline (speedup 1.0000x reference)
#include <cuda_runtime.h>
#include <cuda_bf16.h>
#include <cstdint>

// ===========================================================================
// KANLayer via mma.sync (HMMA) bf16 split-precision GEMM, warp-specialized.
// out[n,o] = sum_k Avirt[n,k]*Bt[o,k] + bias[o],  K = 4608 virtual:
//   k = g*512 + i (g<8): Avirt = exp(-((x[n,i]-grid[g])*1.75)^2), Bt = spline_weight[i*8+g, o]
//   k = 4096 + i:        Avirt = silu(x[n,i]),                    Bt = base_w[o, i]
// 3-pass split: D = Ahi*Bhi + Ahi*Blo + Alo*Bhi  (fp32 accumulators)
// R15: 768 threads = 8 producer warps + 16 consumer warps (4/SMSP) so the
//      HMMA streams 4-way interleave; 32x32 consumer tiles; 3-stage pipeline,
//      B prefetch one chunk ahead, ex2 expansion (from R14).
// ===========================================================================

#define N_ROWS  16384
#define IN_DIM  512
#define OUT_DIM 512
#define KTOT    4608
#define KC      64
#define NCHUNK  72
#define BM      128
#define BN      128
#define NTHREADS 768
#define NSTAGE  3

#define STAGE_BYTES  65536
#define A_HI_OFF(s)  ((s) * STAGE_BYTES + 0)
#define A_LO_OFF(s)  ((s) * STAGE_BYTES + 16384)
#define B_HI_OFF(s)  ((s) * STAGE_BYTES + 32768)
#define B_LO_OFF(s)  ((s) * STAGE_BYTES + 49152)
#define SMEM_TOTAL   (NSTAGE * STAGE_BYTES)

#define BAR_FULL(s)  (1 + (s))
#define BAR_EMPTY(s) (4 + (s))

__device__ __nv_bfloat16 g_Bt_hi[OUT_DIM * KTOT];
__device__ __nv_bfloat16 g_Bt_lo[OUT_DIM * KTOT];

// ---------------- helpers ----------------
__device__ __forceinline__ uint32_t smem_u32(const void* p) {
    uint32_t a;
    asm("{ .reg .u64 t; cvta.to.shared.u64 t, %1; cvt.u32.u64 %0, t; }" : "=r"(a) : "l"(p));
    return a;
}
__device__ __forceinline__ uint32_t swaddr(uint32_t base, int row, int colb) {
    return base + row * 128 + (colb ^ ((row & 7) << 4));
}
__device__ __forceinline__ void ldsm4(uint32_t r[4], uint32_t addr) {
    asm volatile("ldmatrix.sync.aligned.m8n8.x4.shared.b16 {%0,%1,%2,%3}, [%4];"
                 : "=r"(r[0]), "=r"(r[1]), "=r"(r[2]), "=r"(r[3]) : "r"(addr));
}
__device__ __forceinline__ void mma16816(float c[4], const uint32_t a[4],
                                         uint32_t b0, uint32_t b1) {
    asm volatile(
        "mma.sync.aligned.m16n8k16.row.col.f32.bf16.bf16.f32 "
        "{%0,%1,%2,%3}, {%4,%5,%6,%7}, {%8,%9}, {%0,%1,%2,%3};"
        : "+f"(c[0]), "+f"(c[1]), "+f"(c[2]), "+f"(c[3])
        : "r"(a[0]), "r"(a[1]), "r"(a[2]), "r"(a[3]), "r"(b0), "r"(b1));
}
__device__ __forceinline__ void split_bf16(float v, uint16_t& hi, uint16_t& lo) {
    __nv_bfloat16 h = __float2bfloat16(v);
    float r = v - __bfloat162float(h);
    __nv_bfloat16 l = __float2bfloat16(r);
    hi = __bfloat16_as_ushort(h);
    lo = __bfloat16_as_ushort(l);
}
__device__ __forceinline__ uint32_t cvt_bf16x2(float hi_val, float lo_val) {
    uint32_t r;
    asm("cvt.rn.bf16x2.f32 %0, %1, %2;" : "=r"(r) : "f"(hi_val), "f"(lo_val));
    return r;
}
__device__ __forceinline__ float ex2f(float a) {
    float r;
    asm("ex2.approx.f32 %0, %1;" : "=f"(r) : "f"(a));
    return r;
}
__device__ __forceinline__ float rcpf(float a) {
    float r;
    asm("rcp.approx.f32 %0, %1;" : "=f"(r) : "f"(a));
    return r;
}
__device__ __forceinline__ void sts128(uint32_t addr, uint4 v) {
    asm volatile("st.shared.v4.b32 [%0], {%1,%2,%3,%4};"
                 :: "r"(addr), "r"(v.x), "r"(v.y), "r"(v.z), "r"(v.w) : "memory");
}
__device__ __forceinline__ void cp16(uint32_t dst, const void* src) {
    asm volatile("cp.async.cg.shared.global [%0], [%1], 16;"
                 :: "r"(dst), "l"(src) : "memory");
}
#define CP_COMMIT() asm volatile("cp.async.commit_group;" ::: "memory")
#define CP_WAIT0()  asm volatile("cp.async.wait_group 0;" ::: "memory")
#define CP_WAIT1()  asm volatile("cp.async.wait_group 1;" ::: "memory")
__device__ __forceinline__ void bar_sync(int id) {
    asm volatile("bar.sync %0, %1;" :: "r"(id), "n"(NTHREADS) : "memory");
}
__device__ __forceinline__ void bar_arrive(int id) {
    asm volatile("bar.arrive %0, %1;" :: "r"(id), "n"(NTHREADS) : "memory");
}

// ---------------- pre-pass: build Bt_hi/lo ----------------
__global__ void convert_b_kernel(const float* __restrict__ sw,
                                 const float* __restrict__ bw) {
    __shared__ float tile[32][33];
    int g  = blockIdx.z;
    int i0 = blockIdx.x * 32, o0 = blockIdx.y * 32;
    int tx = threadIdx.x, ty = threadIdx.y;
    if (g < 8) {
        #pragma unroll
        for (int j = 0; j < 32; j += 8)
            tile[ty + j][tx] = sw[((size_t)(i0 + ty + j) * 8 + g) * OUT_DIM + o0 + tx];
        __syncthreads();
        #pragma unroll
        for (int j = 0; j < 32; j += 8) {
            float v = tile[tx][ty + j];
            int o = o0 + ty + j, i = i0 + tx;
            uint16_t h, l; split_bf16(v, h, l);
            size_t idx = (size_t)o * KTOT + g * IN_DIM + i;
            g_Bt_hi[idx] = __ushort_as_bfloat16(h);
            g_Bt_lo[idx] = __ushort_as_bfloat16(l);
        }
    } else {
        #pragma unroll
        for (int j = 0; j < 32; j += 8) {
            int o = o0 + ty + j, i = i0 + tx;
            float v = bw[(size_t)o * IN_DIM + i];
            uint16_t h, l; split_bf16(v, h, l);
            size_t idx = (size_t)o * KTOT + 4096 + i;
            g_Bt_hi[idx] = __ushort_as_bfloat16(h);
            g_Bt_lo[idx] = __ushort_as_bfloat16(l);
        }
    }
}

// ---------------- main kernel ----------------
__global__ void __launch_bounds__(NTHREADS, 1)
kan_mma_kernel(const float* __restrict__ x,
               const float* __restrict__ grid,
               const float* __restrict__ bb,
               float* __restrict__ out) {
    extern __shared__ char smem[];
    uint32_t sb = smem_u32(smem);
    const int tid = threadIdx.x;
    const int wid = tid >> 5;
    const int lid = tid & 31;

    const int row0 = blockIdx.y * BM;
    const int n0   = blockIdx.x * BN;

    if (wid < 8) {
        // ================= PRODUCER (threads 0..255) =================
        const int arow = tid >> 1;
        const int half = tid & 1;
        const int brow = tid >> 1;
        const int ub   = (tid & 1) * 4;
        float xs[32];

        // x prologue (ib = 0)
        {
            const float4* xp = reinterpret_cast<const float4*>(
                x + (size_t)(row0 + arow) * IN_DIM + half * 32);
            #pragma unroll
            for (int j = 0; j < 8; j++) {
                float4 v = xp[j];
                xs[4 * j] = v.x; xs[4 * j + 1] = v.y;
                xs[4 * j + 2] = v.z; xs[4 * j + 3] = v.w;
            }
        }
        // B(0) prefetch into stage 0
        {
            size_t goff = (size_t)(n0 + brow) * KTOT + 0 + ub * 8;
            uint32_t bh = sb + B_HI_OFF(0), bl = sb + B_LO_OFF(0);
            #pragma unroll
            for (int u = 0; u < 4; u++) {
                uint32_t d = swaddr(0, brow, (ub + u) * 16);
                cp16(bh + d, g_Bt_hi + goff + u * 8);
                cp16(bl + d, g_Bt_lo + goff + u * 8);
            }
            CP_COMMIT();
        }

        int gg = 0, ib = 0, s = 0;
        for (int c = 0; c < NCHUNK; c++) {
            const int sn  = (s + 1 == NSTAGE) ? 0 : s + 1;
            int ngg = gg + 1, nib = ib;
            if (ngg == 9) { ngg = 0; nib = ib + 1; }

            // ---- prefetch B(c+1) into stage sn ----
            if (c + 1 < NCHUNK) {
                if (c + 1 >= NSTAGE) bar_sync(BAR_EMPTY(sn));
                const int kk = (ngg < 8) ? (ngg * IN_DIM + nib * KC) : (4096 + nib * KC);
                size_t goff = (size_t)(n0 + brow) * KTOT + kk + ub * 8;
                uint32_t bh = sb + B_HI_OFF(sn), bl = sb + B_LO_OFF(sn);
                #pragma unroll
                for (int u = 0; u < 4; u++) {
                    uint32_t d = swaddr(0, brow, (ub + u) * 16);
                    cp16(bh + d, g_Bt_hi + goff + u * 8);
                    cp16(bl + d, g_Bt_lo + goff + u * 8);
                }
                CP_COMMIT();
            }

            // ---- A expansion for chunk c into stage s ----
            {
                const bool is_silu = (gg == 8);
                const float gv = is_silu ? 0.0f : __ldg(grid + gg);
                uint32_t ahb = sb + A_HI_OFF(s);
                uint32_t alb = sb + A_LO_OFF(s);
                #pragma unroll
                for (int c16 = 0; c16 < 4; c16++) {
                    uint32_t hw[4], lw[4];
                    #pragma unroll
                    for (int q = 0; q < 4; q++) {
                        float v0 = xs[c16 * 8 + 2 * q];
                        float v1 = xs[c16 * 8 + 2 * q + 1];
                        float e0, e1;
                        if (!is_silu) {
                            float d0 = v0 - gv, d1 = v1 - gv;
                            e0 = ex2f(-4.418254f * d0 * d0);
                            e1 = ex2f(-4.418254f * d1 * d1);
                        } else {
                            e0 = v0 * rcpf(1.0f + ex2f(-1.442695f * v0));
                            e1 = v1 * rcpf(1.0f + ex2f(-1.442695f * v1));
                        }
                        uint32_t b0 = __float_as_uint(e0);
                        uint32_t b1 = __float_as_uint(e1);
                        hw[q] = __byte_perm(b0, b1, 0x7632);
                        float l0 = e0 - __uint_as_float(b0 & 0xFFFF0000u);
                        float l1 = e1 - __uint_as_float(b1 & 0xFFFF0000u);
                        lw[q] = cvt_bf16x2(l1, l0);
                    }
                    uint32_t d = swaddr(0, arow, half * 64 + c16 * 16);
                    sts128(ahb + d, make_uint4(hw[0], hw[1], hw[2], hw[3]));
                    sts128(alb + d, make_uint4(lw[0], lw[1], lw[2], lw[3]));
                }
            }

            // ---- prefetch x for next ib right after silu consumed old xs ----
            if (gg == 8 && nib < 8) {
                const float4* xp = reinterpret_cast<const float4*>(
                    x + (size_t)(row0 + arow) * IN_DIM + nib * KC + half * 32);
                #pragma unroll
                for (int j = 0; j < 8; j++) {
                    float4 v = xp[j];
                    xs[4 * j] = v.x; xs[4 * j + 1] = v.y;
                    xs[4 * j + 2] = v.z; xs[4 * j + 3] = v.w;
                }
            }

            if (c + 1 < NCHUNK) CP_WAIT1(); else CP_WAIT0();
            bar_arrive(BAR_FULL(s));

            gg = ngg; ib = nib; s = sn;
        }
    } else {
        // ================= CONSUMER (threads 256..767, 16 warps) =============
        const int wc = wid - 8;        // 0..15
        const int wm = wc & 3;         // row block: wm*32 .. +31
        const int wn = wc >> 2;        // col block: wn*32 .. +31

        float acc[2][4][4];
        #pragma unroll
        for (int mt = 0; mt < 2; mt++)
            #pragma unroll
            for (int nt = 0; nt < 4; nt++)
                #pragma unroll
                for (int q = 0; q < 4; q++) acc[mt][nt][q] = 0.0f;

        const int bno   = (lid & 7) + ((lid >> 4) << 3);
        const int bcsel = ((lid >> 3) & 1) << 4;
        const int arow  = lid & 15;
        const int acsel = (lid >> 4) << 4;

        int s = 0;
        for (int c = 0; c < NCHUNK; c++) {
            bar_sync(BAR_FULL(s));

            const uint32_t Ah = sb + A_HI_OFF(s), Al = sb + A_LO_OFF(s);
            const uint32_t Bh = sb + B_HI_OFF(s), Bl = sb + B_LO_OFF(s);
            #pragma unroll
            for (int ks = 0; ks < 4; ks++) {
                const int acolb = ks * 32 + acsel;
                uint32_t ahf[2][4], alf[2][4];
                #pragma unroll
                for (int mt = 0; mt < 2; mt++) {
                    int row = wm * 32 + mt * 16 + arow;
                    ldsm4(ahf[mt], swaddr(Ah, row, acolb));
                    ldsm4(alf[mt], swaddr(Al, row, acolb));
                }
                const int bcolb = ks * 32 + bcsel;
                #pragma unroll
                for (int p = 0; p < 2; p++) {
                    uint32_t bh4[4], bl4[4];
                    int brow = wn * 32 + p * 16 + bno;
                    ldsm4(bh4, swaddr(Bh, brow, bcolb));
                    ldsm4(bl4, swaddr(Bl, brow, bcolb));
                    #pragma unroll
                    for (int mt = 0; mt < 2; mt++) {
                        #pragma unroll
                        for (int j = 0; j < 2; j++) {
                            const int nt = p * 2 + j;
                            mma16816(acc[mt][nt], ahf[mt], bh4[j * 2], bh4[j * 2 + 1]);
                            mma16816(acc[mt][nt], ahf[mt], bl4[j * 2], bl4[j * 2 + 1]);
                            mma16816(acc[mt][nt], alf[mt], bh4[j * 2], bh4[j * 2 + 1]);
                        }
                    }
                }
            }

            bar_arrive(BAR_EMPTY(s));
            if (++s == NSTAGE) s = 0;
        }

        // ---- epilogue: bias + store ----
        #pragma unroll
        for (int mt = 0; mt < 2; mt++) {
            int row = row0 + wm * 32 + mt * 16 + (lid >> 2);
            #pragma unroll
            for (int nt = 0; nt < 4; nt++) {
                int col = n0 + wn * 32 + nt * 8 + (lid & 3) * 2;
                float2 bv = *reinterpret_cast<const float2*>(bb + col);
                float2 o0, o1;
                o0.x = acc[mt][nt][0] + bv.x;
                o0.y = acc[mt][nt][1] + bv.y;
                o1.x = acc[mt][nt][2] + bv.x;
                o1.y = acc[mt][nt][3] + bv.y;
                *reinterpret_cast<float2*>(out + (size_t)row * OUT_DIM + col) = o0;
                *reinterpret_cast<float2*>(out + (size_t)(row + 8) * OUT_DIM + col) = o1;
            }
        }
    }
}

// ---------------- launch ----------------
extern "C" void kernel_launch(void* const* d_in, const int* in_sizes, int n_in,
                              void* d_out, int out_size) {
    const float* x    = (const float*)d_in[0];
    const float* grid = (const float*)d_in[1];
    const float* sw   = (const float*)d_in[2];
    const float* bw   = (const float*)d_in[3];
    const float* bb   = (const float*)d_in[4];
    float* out = (float*)d_out;

    convert_b_kernel<<<dim3(16, 16, 9), dim3(32, 8)>>>(sw, bw);

    cudaFuncSetAttribute(kan_mma_kernel, cudaFuncAttributeMaxDynamicSharedMemorySize,
                         SMEM_TOTAL);
    dim3 g(OUT_DIM / BN, N_ROWS / BM);   // (4, 128) = 512 CTAs
    kan_mma_kernel<<<g, NTHREADS, SMEM_TOTAL>>>(x, grid, bb, out);
}

// round 16
// speedup vs baseline: 1.0451x; 1.0451x over previous
#include <cuda_runtime.h>
#include <cuda_bf16.h>
#include <cstdint>

// ===========================================================================
// KANLayer via mma.sync (HMMA) bf16 split-precision GEMM, warp-specialized.
// out[n,o] = sum_k Avirt[n,k]*Bt[o,k] + bias[o],  K = 4608 virtual:
//   k = g*512 + i (g<8): Avirt = exp(-((x[n,i]-grid[g])*1.75)^2), Bt = spline_weight[i*8+g, o]
//   k = 4096 + i:        Avirt = silu(x[n,i]),                    Bt = base_w[o, i]
// 3-pass split: D = Ahi*Bhi + Ahi*Blo + Alo*Bhi  (fp32 accumulators)
// R16 = R14 (512 thr, 8P+8C warps, 3 stages, B prefetch 1 ahead, ex2) with
//       the consumer MMA loop reordered PASS-MAJOR: same-accumulator reuse
//       distance 1 -> 4 instructions, so HMMA latency is covered.
// ===========================================================================

#define N_ROWS  16384
#define IN_DIM  512
#define OUT_DIM 512
#define KTOT    4608
#define KC      64
#define NCHUNK  72
#define BM      128
#define BN      128
#define NTHREADS 512
#define NSTAGE  3

#define STAGE_BYTES  65536
#define A_HI_OFF(s)  ((s) * STAGE_BYTES + 0)
#define A_LO_OFF(s)  ((s) * STAGE_BYTES + 16384)
#define B_HI_OFF(s)  ((s) * STAGE_BYTES + 32768)
#define B_LO_OFF(s)  ((s) * STAGE_BYTES + 49152)
#define SMEM_TOTAL   (NSTAGE * STAGE_BYTES)

#define BAR_FULL(s)  (1 + (s))
#define BAR_EMPTY(s) (4 + (s))

__device__ __nv_bfloat16 g_Bt_hi[OUT_DIM * KTOT];
__device__ __nv_bfloat16 g_Bt_lo[OUT_DIM * KTOT];

// ---------------- helpers ----------------
__device__ __forceinline__ uint32_t smem_u32(const void* p) {
    uint32_t a;
    asm("{ .reg .u64 t; cvta.to.shared.u64 t, %1; cvt.u32.u64 %0, t; }" : "=r"(a) : "l"(p));
    return a;
}
__device__ __forceinline__ uint32_t swaddr(uint32_t base, int row, int colb) {
    return base + row * 128 + (colb ^ ((row & 7) << 4));
}
__device__ __forceinline__ void ldsm4(uint32_t r[4], uint32_t addr) {
    asm volatile("ldmatrix.sync.aligned.m8n8.x4.shared.b16 {%0,%1,%2,%3}, [%4];"
                 : "=r"(r[0]), "=r"(r[1]), "=r"(r[2]), "=r"(r[3]) : "r"(addr));
}
__device__ __forceinline__ void mma16816(float c[4], const uint32_t a[4],
                                         uint32_t b0, uint32_t b1) {
    asm volatile(
        "mma.sync.aligned.m16n8k16.row.col.f32.bf16.bf16.f32 "
        "{%0,%1,%2,%3}, {%4,%5,%6,%7}, {%8,%9}, {%0,%1,%2,%3};"
        : "+f"(c[0]), "+f"(c[1]), "+f"(c[2]), "+f"(c[3])
        : "r"(a[0]), "r"(a[1]), "r"(a[2]), "r"(a[3]), "r"(b0), "r"(b1));
}
__device__ __forceinline__ void split_bf16(float v, uint16_t& hi, uint16_t& lo) {
    __nv_bfloat16 h = __float2bfloat16(v);
    float r = v - __bfloat162float(h);
    __nv_bfloat16 l = __float2bfloat16(r);
    hi = __bfloat16_as_ushort(h);
    lo = __bfloat16_as_ushort(l);
}
__device__ __forceinline__ uint32_t cvt_bf16x2(float hi_val, float lo_val) {
    uint32_t r;
    asm("cvt.rn.bf16x2.f32 %0, %1, %2;" : "=r"(r) : "f"(hi_val), "f"(lo_val));
    return r;
}
__device__ __forceinline__ float ex2f(float a) {
    float r;
    asm("ex2.approx.f32 %0, %1;" : "=f"(r) : "f"(a));
    return r;
}
__device__ __forceinline__ float rcpf(float a) {
    float r;
    asm("rcp.approx.f32 %0, %1;" : "=f"(r) : "f"(a));
    return r;
}
__device__ __forceinline__ void sts128(uint32_t addr, uint4 v) {
    asm volatile("st.shared.v4.b32 [%0], {%1,%2,%3,%4};"
                 :: "r"(addr), "r"(v.x), "r"(v.y), "r"(v.z), "r"(v.w) : "memory");
}
__device__ __forceinline__ void cp16(uint32_t dst, const void* src) {
    asm volatile("cp.async.cg.shared.global [%0], [%1], 16;"
                 :: "r"(dst), "l"(src) : "memory");
}
#define CP_COMMIT() asm volatile("cp.async.commit_group;" ::: "memory")
#define CP_WAIT0()  asm volatile("cp.async.wait_group 0;" ::: "memory")
#define CP_WAIT1()  asm volatile("cp.async.wait_group 1;" ::: "memory")
__device__ __forceinline__ void bar_sync(int id) {
    asm volatile("bar.sync %0, %1;" :: "r"(id), "n"(NTHREADS) : "memory");
}
__device__ __forceinline__ void bar_arrive(int id) {
    asm volatile("bar.arrive %0, %1;" :: "r"(id), "n"(NTHREADS) : "memory");
}

// ---------------- pre-pass: build Bt_hi/lo ----------------
__global__ void convert_b_kernel(const float* __restrict__ sw,
                                 const float* __restrict__ bw) {
    __shared__ float tile[32][33];
    int g  = blockIdx.z;
    int i0 = blockIdx.x * 32, o0 = blockIdx.y * 32;
    int tx = threadIdx.x, ty = threadIdx.y;
    if (g < 8) {
        #pragma unroll
        for (int j = 0; j < 32; j += 8)
            tile[ty + j][tx] = sw[((size_t)(i0 + ty + j) * 8 + g) * OUT_DIM + o0 + tx];
        __syncthreads();
        #pragma unroll
        for (int j = 0; j < 32; j += 8) {
            float v = tile[tx][ty + j];
            int o = o0 + ty + j, i = i0 + tx;
            uint16_t h, l; split_bf16(v, h, l);
            size_t idx = (size_t)o * KTOT + g * IN_DIM + i;
            g_Bt_hi[idx] = __ushort_as_bfloat16(h);
            g_Bt_lo[idx] = __ushort_as_bfloat16(l);
        }
    } else {
        #pragma unroll
        for (int j = 0; j < 32; j += 8) {
            int o = o0 + ty + j, i = i0 + tx;
            float v = bw[(size_t)o * IN_DIM + i];
            uint16_t h, l; split_bf16(v, h, l);
            size_t idx = (size_t)o * KTOT + 4096 + i;
            g_Bt_hi[idx] = __ushort_as_bfloat16(h);
            g_Bt_lo[idx] = __ushort_as_bfloat16(l);
        }
    }
}

// ---------------- main kernel ----------------
__global__ void __launch_bounds__(NTHREADS, 1)
kan_mma_kernel(const float* __restrict__ x,
               const float* __restrict__ grid,
               const float* __restrict__ bb,
               float* __restrict__ out) {
    extern __shared__ char smem[];
    uint32_t sb = smem_u32(smem);
    const int tid = threadIdx.x;
    const int wid = tid >> 5;
    const int lid = tid & 31;

    const int row0 = blockIdx.y * BM;
    const int n0   = blockIdx.x * BN;

    if (wid < 8) {
        // ================= PRODUCER (threads 0..255) =================
        const int arow = tid >> 1;
        const int half = tid & 1;
        const int brow = tid >> 1;
        const int ub   = (tid & 1) * 4;
        float xs[32];

        // x prologue (ib = 0)
        {
            const float4* xp = reinterpret_cast<const float4*>(
                x + (size_t)(row0 + arow) * IN_DIM + half * 32);
            #pragma unroll
            for (int j = 0; j < 8; j++) {
                float4 v = xp[j];
                xs[4 * j] = v.x; xs[4 * j + 1] = v.y;
                xs[4 * j + 2] = v.z; xs[4 * j + 3] = v.w;
            }
        }
        // B(0) prefetch into stage 0
        {
            size_t goff = (size_t)(n0 + brow) * KTOT + 0 + ub * 8;
            uint32_t bh = sb + B_HI_OFF(0), bl = sb + B_LO_OFF(0);
            #pragma unroll
            for (int u = 0; u < 4; u++) {
                uint32_t d = swaddr(0, brow, (ub + u) * 16);
                cp16(bh + d, g_Bt_hi + goff + u * 8);
                cp16(bl + d, g_Bt_lo + goff + u * 8);
            }
            CP_COMMIT();
        }

        int gg = 0, ib = 0, s = 0;
        for (int c = 0; c < NCHUNK; c++) {
            const int sn  = (s + 1 == NSTAGE) ? 0 : s + 1;
            int ngg = gg + 1, nib = ib;
            if (ngg == 9) { ngg = 0; nib = ib + 1; }

            // ---- prefetch B(c+1) into stage sn ----
            if (c + 1 < NCHUNK) {
                if (c + 1 >= NSTAGE) bar_sync(BAR_EMPTY(sn));
                const int kk = (ngg < 8) ? (ngg * IN_DIM + nib * KC) : (4096 + nib * KC);
                size_t goff = (size_t)(n0 + brow) * KTOT + kk + ub * 8;
                uint32_t bh = sb + B_HI_OFF(sn), bl = sb + B_LO_OFF(sn);
                #pragma unroll
                for (int u = 0; u < 4; u++) {
                    uint32_t d = swaddr(0, brow, (ub + u) * 16);
                    cp16(bh + d, g_Bt_hi + goff + u * 8);
                    cp16(bl + d, g_Bt_lo + goff + u * 8);
                }
                CP_COMMIT();
            }

            // ---- A expansion for chunk c into stage s ----
            {
                const bool is_silu = (gg == 8);
                const float gv = is_silu ? 0.0f : __ldg(grid + gg);
                uint32_t ahb = sb + A_HI_OFF(s);
                uint32_t alb = sb + A_LO_OFF(s);
                #pragma unroll
                for (int c16 = 0; c16 < 4; c16++) {
                    uint32_t hw[4], lw[4];
                    #pragma unroll
                    for (int q = 0; q < 4; q++) {
                        float v0 = xs[c16 * 8 + 2 * q];
                        float v1 = xs[c16 * 8 + 2 * q + 1];
                        float e0, e1;
                        if (!is_silu) {
                            float d0 = v0 - gv, d1 = v1 - gv;
                            e0 = ex2f(-4.418254f * d0 * d0);
                            e1 = ex2f(-4.418254f * d1 * d1);
                        } else {
                            e0 = v0 * rcpf(1.0f + ex2f(-1.442695f * v0));
                            e1 = v1 * rcpf(1.0f + ex2f(-1.442695f * v1));
                        }
                        uint32_t b0 = __float_as_uint(e0);
                        uint32_t b1 = __float_as_uint(e1);
                        hw[q] = __byte_perm(b0, b1, 0x7632);
                        float l0 = e0 - __uint_as_float(b0 & 0xFFFF0000u);
                        float l1 = e1 - __uint_as_float(b1 & 0xFFFF0000u);
                        lw[q] = cvt_bf16x2(l1, l0);
                    }
                    uint32_t d = swaddr(0, arow, half * 64 + c16 * 16);
                    sts128(ahb + d, make_uint4(hw[0], hw[1], hw[2], hw[3]));
                    sts128(alb + d, make_uint4(lw[0], lw[1], lw[2], lw[3]));
                }
            }

            // ---- prefetch x for next ib right after silu consumed old xs ----
            if (gg == 8 && nib < 8) {
                const float4* xp = reinterpret_cast<const float4*>(
                    x + (size_t)(row0 + arow) * IN_DIM + nib * KC + half * 32);
                #pragma unroll
                for (int j = 0; j < 8; j++) {
                    float4 v = xp[j];
                    xs[4 * j] = v.x; xs[4 * j + 1] = v.y;
                    xs[4 * j + 2] = v.z; xs[4 * j + 3] = v.w;
                }
            }

            if (c + 1 < NCHUNK) CP_WAIT1(); else CP_WAIT0();
            bar_arrive(BAR_FULL(s));

            gg = ngg; ib = nib; s = sn;
        }
    } else {
        // ================= CONSUMER (threads 256..511) =================
        const int wc = wid - 8;
        const int wm = wc & 3;
        const int wn = wc >> 2;

        float acc[2][8][4];
        #pragma unroll
        for (int mt = 0; mt < 2; mt++)
            #pragma unroll
            for (int nt = 0; nt < 8; nt++)
                #pragma unroll
                for (int q = 0; q < 4; q++) acc[mt][nt][q] = 0.0f;

        const int bno   = (lid & 7) + ((lid >> 4) << 3);
        const int bcsel = ((lid >> 3) & 1) << 4;
        const int arow  = lid & 15;
        const int acsel = (lid >> 4) << 4;

        int s = 0;
        for (int c = 0; c < NCHUNK; c++) {
            bar_sync(BAR_FULL(s));

            const uint32_t Ah = sb + A_HI_OFF(s), Al = sb + A_LO_OFF(s);
            const uint32_t Bh = sb + B_HI_OFF(s), Bl = sb + B_LO_OFF(s);
            #pragma unroll
            for (int ks = 0; ks < 4; ks++) {
                const int acolb = ks * 32 + acsel;
                uint32_t ahf[2][4], alf[2][4];
                #pragma unroll
                for (int mt = 0; mt < 2; mt++) {
                    int row = wm * 32 + mt * 16 + arow;
                    ldsm4(ahf[mt], swaddr(Ah, row, acolb));
                    ldsm4(alf[mt], swaddr(Al, row, acolb));
                }
                const int bcolb = ks * 32 + bcsel;
                #pragma unroll
                for (int p = 0; p < 4; p++) {
                    uint32_t bh4[4], bl4[4];
                    int brow = wn * 64 + p * 16 + bno;
                    ldsm4(bh4, swaddr(Bh, brow, bcolb));
                    ldsm4(bl4, swaddr(Bl, brow, bcolb));
                    // PASS-MAJOR: all tiles for hi*hi, then hi*lo, then lo*hi.
                    // Same-accumulator reuse distance = 4 MMAs (covers HMMA lat).
                    #pragma unroll
                    for (int mt = 0; mt < 2; mt++)
                        #pragma unroll
                        for (int j = 0; j < 2; j++)
                            mma16816(acc[mt][p * 2 + j], ahf[mt],
                                     bh4[j * 2], bh4[j * 2 + 1]);      // hi*hi
                    #pragma unroll
                    for (int mt = 0; mt < 2; mt++)
                        #pragma unroll
                        for (int j = 0; j < 2; j++)
                            mma16816(acc[mt][p * 2 + j], ahf[mt],
                                     bl4[j * 2], bl4[j * 2 + 1]);      // hi*lo
                    #pragma unroll
                    for (int mt = 0; mt < 2; mt++)
                        #pragma unroll
                        for (int j = 0; j < 2; j++)
                            mma16816(acc[mt][p * 2 + j], alf[mt],
                                     bh4[j * 2], bh4[j * 2 + 1]);      // lo*hi
                }
            }

            bar_arrive(BAR_EMPTY(s));
            if (++s == NSTAGE) s = 0;
        }

        // ---- epilogue: bias + store ----
        #pragma unroll
        for (int mt = 0; mt < 2; mt++) {
            int row = row0 + wm * 32 + mt * 16 + (lid >> 2);
            #pragma unroll
            for (int nt = 0; nt < 8; nt++) {
                int col = n0 + wn * 64 + nt * 8 + (lid & 3) * 2;
                float2 bv = *reinterpret_cast<const float2*>(bb + col);
                float2 o0, o1;
                o0.x = acc[mt][nt][0] + bv.x;
                o0.y = acc[mt][nt][1] + bv.y;
                o1.x = acc[mt][nt][2] + bv.x;
                o1.y = acc[mt][nt][3] + bv.y;
                *reinterpret_cast<float2*>(out + (size_t)row * OUT_DIM + col) = o0;
                *reinterpret_cast<float2*>(out + (size_t)(row + 8) * OUT_DIM + col) = o1;
            }
        }
    }
}

// ---------------- launch ----------------
extern "C" void kernel_launch(void* const* d_in, const int* in_sizes, int n_in,
                              void* d_out, int out_size) {
    const float* x    = (const float*)d_in[0];
    const float* grid = (const float*)d_in[1];
    const float* sw   = (const float*)d_in[2];
    const float* bw   = (const float*)d_in[3];
    const float* bb   = (const float*)d_in[4];
    float* out = (float*)d_out;

    convert_b_kernel<<<dim3(16, 16, 9), dim3(32, 8)>>>(sw, bw);

    cudaFuncSetAttribute(kan_mma_kernel, cudaFuncAttributeMaxDynamicSharedMemorySize,
                         SMEM_TOTAL);
    dim3 g(OUT_DIM / BN, N_ROWS / BM);   // (4, 128) = 512 CTAs
    kan_mma_kernel<<<g, NTHREADS, SMEM_TOTAL>>>(x, grid, bb, out);
}